// round 2
// baseline (speedup 1.0000x reference)
#include <cuda_runtime.h>
#include <cstddef>

#define MD 4
#define ND 9            // 2*MD+1
#define NB 4
#define NC 64
#define NH 192
#define NW 320
#define HW (NH*NW)

#define TW 64
#define TH 4
#define NTHR 288        // 8 xgroups * 4 rows * 9 dy
#define CCH 4           // channels per chunk
#define NCHUNK (NC/CCH) // 16

#define SPITCH 76       // 72 cols (64 + 2*4 halo) + 4 pad
#define SROWS 12        // 4 rows + 2*4 halo
#define FPITCH 64
#define S_CH_STRIDE (SROWS*SPITCH)      // 912 floats
#define S_BUF_STRIDE (CCH*S_CH_STRIDE)  // 3648 floats
#define F_CH_STRIDE (TH*FPITCH)         // 256 floats
#define F_BUF_STRIDE (CCH*F_CH_STRIDE)  // 1024 floats

__device__ __forceinline__ void cp_async16(float* smem, const float* gmem) {
    unsigned saddr = (unsigned)__cvta_generic_to_shared(smem);
    asm volatile("cp.async.cg.shared.global [%0], [%1], 16;\n" :: "r"(saddr), "l"(gmem));
}
__device__ __forceinline__ void cp_commit() { asm volatile("cp.async.commit_group;\n" ::: "memory"); }
__device__ __forceinline__ void cp_wait0()  { asm volatile("cp.async.wait_group 0;\n" ::: "memory"); }

__global__ void __launch_bounds__(NTHR, 1)
corr_kernel(const float* __restrict__ F, const float* __restrict__ S, float* __restrict__ out)
{
    __shared__ __align__(16) float sS[2*S_BUF_STRIDE];
    __shared__ __align__(16) float sF[2*F_BUF_STRIDE];

    const int tid = threadIdx.x;
    const int w0  = blockIdx.x * TW;
    const int h0  = blockIdx.y * TH;
    const int b   = blockIdx.z;

    const int xg  = tid & 7;
    const int row = (tid >> 3) & 3;
    const int dy  = tid >> 5;        // 0..8
    const int x0  = xg * 8;

    // ---- per-thread cp.async assignments (block-constant) ----
    // S tile: 4ch * 12rows * 18 float4 = 864 items = 3 per thread
    int          s_sofs[3];
    const float* s_gptr[3];
    bool         s_valid[3];
    const float* Sbase = S + (size_t)b * NC * HW;
    #pragma unroll
    for (int t = 0; t < 3; t++) {
        int i   = tid + NTHR * t;
        int ch  = i / 216;
        int rem = i % 216;
        int r   = rem / 18;
        int j   = rem % 18;
        int gr  = h0 + r - MD;
        int gc  = w0 - MD + 4*j;
        bool v  = (gr >= 0) && (gr < NH) && (gc >= 0) && (gc < NW);
        s_valid[t] = v;
        s_sofs[t]  = ch * S_CH_STRIDE + r * SPITCH + 4*j;
        s_gptr[t]  = Sbase + (size_t)ch * HW + (v ? (gr*NW + gc) : 0);
    }
    // F tile: 4ch * 4rows * 16 float4 = 256 items (tid < 256), always in-range
    const bool f_active = (tid < 256);
    int f_sofs;
    const float* f_gptr;
    {
        int ch = tid >> 6;
        int r  = (tid >> 4) & 3;
        int j  = tid & 15;
        f_sofs = ch * F_CH_STRIDE + r * FPITCH + 4*j;
        f_gptr = F + (size_t)b * NC * HW + (size_t)ch * HW + (h0 + r) * NW + (w0 + 4*j);
    }

    // zero-fill OOB padding slots once (validity identical for every chunk)
    #pragma unroll
    for (int t = 0; t < 3; t++) {
        if (!s_valid[t]) {
            float4 z = make_float4(0.f, 0.f, 0.f, 0.f);
            *(float4*)&sS[s_sofs[t]]                = z;
            *(float4*)&sS[S_BUF_STRIDE + s_sofs[t]] = z;
        }
    }

    // prefetch chunk 0 into buffer 0
    #pragma unroll
    for (int t = 0; t < 3; t++)
        if (s_valid[t]) cp_async16(&sS[s_sofs[t]], s_gptr[t]);
    if (f_active) cp_async16(&sF[f_sofs], f_gptr);
    cp_commit();

    float acc[ND][8];
    #pragma unroll
    for (int dx = 0; dx < ND; dx++)
        #pragma unroll
        for (int p = 0; p < 8; p++) acc[dx][p] = 0.f;

    const int srow_ofs = (row + dy) * SPITCH + x0;  // S tile row for this (row, dy)
    const int frow_ofs = row * FPITCH + x0;

    for (int k = 0; k < NCHUNK; k++) {
        cp_wait0();
        __syncthreads();   // chunk-k data visible to all; all warps done with buf k-1

        // prefetch chunk k+1 into the other buffer (overlaps with compute below)
        if (k + 1 < NCHUNK) {
            const int nbuf = (k + 1) & 1;
            const size_t cofs = (size_t)(k + 1) * CCH * HW;
            #pragma unroll
            for (int t = 0; t < 3; t++)
                if (s_valid[t]) cp_async16(&sS[nbuf*S_BUF_STRIDE + s_sofs[t]], s_gptr[t] + cofs);
            if (f_active) cp_async16(&sF[nbuf*F_BUF_STRIDE + f_sofs], f_gptr + cofs);
        }
        cp_commit();

        const int buf = k & 1;
        const float* sSb = &sS[buf*S_BUF_STRIDE + srow_ofs];
        const float* sFb = &sF[buf*F_BUF_STRIDE + frow_ofs];
        #pragma unroll
        for (int cc = 0; cc < CCH; cc++) {
            float4 s0 = *(const float4*)(sSb + cc*S_CH_STRIDE);
            float4 s1 = *(const float4*)(sSb + cc*S_CH_STRIDE + 4);
            float4 s2 = *(const float4*)(sSb + cc*S_CH_STRIDE + 8);
            float4 s3 = *(const float4*)(sSb + cc*S_CH_STRIDE + 12);
            float sv[16] = {s0.x,s0.y,s0.z,s0.w, s1.x,s1.y,s1.z,s1.w,
                            s2.x,s2.y,s2.z,s2.w, s3.x,s3.y,s3.z,s3.w};
            float4 f0 = *(const float4*)(sFb + cc*F_CH_STRIDE);
            float4 f1 = *(const float4*)(sFb + cc*F_CH_STRIDE + 4);
            float fv[8] = {f0.x,f0.y,f0.z,f0.w, f1.x,f1.y,f1.z,f1.w};
            #pragma unroll
            for (int dx = 0; dx < ND; dx++)
                #pragma unroll
                for (int p = 0; p < 8; p++)
                    acc[dx][p] = fmaf(fv[p], sv[dx + p], acc[dx][p]);
        }
    }

    // ---- epilogue: scale by 1/C and store (vectorized, coalesced) ----
    const float scale = 1.0f / (float)NC;
    float* obase = out + (((size_t)b * (ND*ND) + (size_t)dy * ND) * NH + (h0 + row)) * NW
                       + (w0 + x0);
    #pragma unroll
    for (int dx = 0; dx < ND; dx++) {
        float* o = obase + (size_t)dx * NH * NW;
        float4 v0 = make_float4(acc[dx][0]*scale, acc[dx][1]*scale,
                                acc[dx][2]*scale, acc[dx][3]*scale);
        float4 v1 = make_float4(acc[dx][4]*scale, acc[dx][5]*scale,
                                acc[dx][6]*scale, acc[dx][7]*scale);
        *(float4*)o       = v0;
        *(float4*)(o + 4) = v1;
    }
}

extern "C" void kernel_launch(void* const* d_in, const int* in_sizes, int n_in,
                              void* d_out, int out_size)
{
    const float* tenFirst  = (const float*)d_in[0];
    const float* tenSecond = (const float*)d_in[1];
    float* out = (float*)d_out;

    dim3 grid(NW / TW, NH / TH, NB);   // 5 x 48 x 4 = 960 blocks
    dim3 block(NTHR);
    corr_kernel<<<grid, block>>>(tenFirst, tenSecond, out);
}

// round 6
// speedup vs baseline: 1.1858x; 1.1858x over previous
#include <cuda_runtime.h>
#include <cstddef>

#define MD 4
#define ND 9            // 2*MD+1
#define NB 4
#define NC 64
#define NH 192
#define NW 320
#define HW (NH*NW)

#define TW 32
#define TH 8
#define NTHR 576        // 8 xgroups * 8 rows * 9 dy
#define CCH 4           // channels per chunk
#define NCHUNK (NC/CCH) // 16
#define NSTAGE 3

#define SPITCH 44       // 40 data cols (32 + 2*4 halo) + 4 pad
#define SROWS 16        // 8 rows + 2*4 halo
#define FPITCH 32
#define S_CH_STRIDE (SROWS*SPITCH)      // 704 floats
#define S_BUF_STRIDE (CCH*S_CH_STRIDE)  // 2816 floats
#define F_CH_STRIDE (TH*FPITCH)         // 256 floats
#define F_BUF_STRIDE (CCH*F_CH_STRIDE)  // 1024 floats

__device__ __forceinline__ void cp_async16(float* smem, const float* gmem) {
    unsigned saddr = (unsigned)__cvta_generic_to_shared(smem);
    asm volatile("cp.async.cg.shared.global [%0], [%1], 16;\n" :: "r"(saddr), "l"(gmem));
}
__device__ __forceinline__ void cp_commit() { asm volatile("cp.async.commit_group;\n" ::: "memory"); }
__device__ __forceinline__ void cp_wait0()  { asm volatile("cp.async.wait_group 0;\n" ::: "memory"); }
__device__ __forceinline__ void cp_wait1()  { asm volatile("cp.async.wait_group 1;\n" ::: "memory"); }

// packed f32x2 helpers (sm_103a)
__device__ __forceinline__ unsigned long long ffma2(unsigned long long a,
                                                    unsigned long long b,
                                                    unsigned long long c) {
    unsigned long long d;
    asm("fma.rn.f32x2 %0, %1, %2, %3;" : "=l"(d) : "l"(a), "l"(b), "l"(c));
    return d;
}
__device__ __forceinline__ unsigned long long pack2(float lo, float hi) {
    unsigned long long r;
    asm("mov.b64 %0, {%1, %2};" : "=l"(r)
        : "r"(__float_as_uint(lo)), "r"(__float_as_uint(hi)));
    return r;
}
__device__ __forceinline__ void unpack2(unsigned long long v, float& lo, float& hi) {
    unsigned a, b;
    asm("mov.b64 {%0, %1}, %2;" : "=r"(a), "=r"(b) : "l"(v));
    lo = __uint_as_float(a); hi = __uint_as_float(b);
}

union F4U {
    float4 v;
    unsigned long long u[2];
    float f[4];
};

__global__ void __launch_bounds__(NTHR, 1)
corr_kernel(const float* __restrict__ F, const float* __restrict__ S, float* __restrict__ out)
{
    __shared__ __align__(16) float sS[NSTAGE*S_BUF_STRIDE];
    __shared__ __align__(16) float sF[NSTAGE*F_BUF_STRIDE];

    const int tid = threadIdx.x;
    const int w0  = blockIdx.x * TW;
    const int h0  = blockIdx.y * TH;
    const int b   = blockIdx.z;

    const int xg  = tid & 7;
    const int row = (tid >> 3) & 7;
    const int dy  = tid >> 6;        // 0..8
    const int x0  = xg * 4;

    // ---- per-thread cp.async assignments (block-constant) ----
    // S tile: 4ch * 16rows * 10 float4 = 640 items; <=2 per thread
    int          s_sofs[2];
    const float* s_gptr[2];
    bool         s_valid[2];
    bool         s_act[2];
    const float* Sbase = S + (size_t)b * NC * HW;
    #pragma unroll
    for (int t = 0; t < 2; t++) {
        int i   = tid + NTHR * t;
        bool act = (i < 640);
        s_act[t] = act;
        int ii  = act ? i : 0;
        int ch  = ii / 160;
        int rem = ii % 160;
        int r   = rem / 10;
        int j   = rem % 10;
        int gr  = h0 + r - MD;
        int gc  = w0 - MD + 4*j;
        bool v  = (gr >= 0) && (gr < NH) && (gc >= 0) && (gc < NW);
        s_valid[t] = v;
        s_sofs[t]  = ch * S_CH_STRIDE + r * SPITCH + 4*j;
        s_gptr[t]  = Sbase + (size_t)ch * HW + (v ? (gr*NW + gc) : 0);
    }
    // F tile: 4ch * 8rows * 8 float4 = 256 items (tid < 256), always in-range
    const bool f_active = (tid < 256);
    int f_sofs;
    const float* f_gptr;
    {
        int ch = tid >> 6;
        int r  = (tid >> 3) & 7;
        int j  = tid & 7;
        f_sofs = ch * F_CH_STRIDE + r * FPITCH + 4*j;
        f_gptr = F + (size_t)b * NC * HW + (size_t)ch * HW + (h0 + r) * NW + (w0 + 4*j);
    }

    // zero-fill OOB padding slots once in all stages (validity identical per chunk)
    #pragma unroll
    for (int t = 0; t < 2; t++) {
        if (s_act[t] && !s_valid[t]) {
            float4 z = make_float4(0.f, 0.f, 0.f, 0.f);
            #pragma unroll
            for (int st = 0; st < NSTAGE; st++)
                *(float4*)&sS[st*S_BUF_STRIDE + s_sofs[t]] = z;
        }
    }

    auto issue = [&](int k) {
        const int stg = k % NSTAGE;
        const size_t cofs = (size_t)k * CCH * HW;
        #pragma unroll
        for (int t = 0; t < 2; t++)
            if (s_act[t] && s_valid[t])
                cp_async16(&sS[stg*S_BUF_STRIDE + s_sofs[t]], s_gptr[t] + cofs);
        if (f_active)
            cp_async16(&sF[stg*F_BUF_STRIDE + f_sofs], f_gptr + cofs);
        cp_commit();
    };

    // prologue: chunks 0 and 1 in flight
    issue(0);
    issue(1);

    // packed accumulators: acc2[dx][q] holds pixels (2q, 2q+1)
    unsigned long long acc2[ND][2];
    #pragma unroll
    for (int dx = 0; dx < ND; dx++) { acc2[dx][0] = 0ull; acc2[dx][1] = 0ull; }

    const int srow_ofs = (row + dy) * SPITCH + x0;
    const int frow_ofs = row * FPITCH + x0;

    int buf = 0;
    #pragma unroll 1
    for (int k = 0; k < NCHUNK; k++) {
        if (k < NCHUNK - 1) cp_wait1(); else cp_wait0();
        __syncthreads();   // chunk-k data visible; all warps done with the buf being refilled

        if (k + 2 < NCHUNK) issue(k + 2);

        const float* sSb = &sS[buf*S_BUF_STRIDE + srow_ofs];
        const float* sFb = &sF[buf*F_BUF_STRIDE + frow_ofs];
        #pragma unroll
        for (int cc = 0; cc < CCH; cc++) {
            F4U s0, s1, s2, f0;
            s0.v = *(const float4*)(sSb + cc*S_CH_STRIDE);
            s1.v = *(const float4*)(sSb + cc*S_CH_STRIDE + 4);
            s2.v = *(const float4*)(sSb + cc*S_CH_STRIDE + 8);
            f0.v = *(const float4*)(sFb + cc*F_CH_STRIDE);
            // P[i] = (sv[i], sv[i+1]), i = 0..10
            unsigned long long P[11];
            P[0]  = s0.u[0];  P[2]  = s0.u[1];
            P[4]  = s1.u[0];  P[6]  = s1.u[1];
            P[8]  = s2.u[0];  P[10] = s2.u[1];
            P[1]  = pack2(s0.f[1], s0.f[2]);
            P[3]  = pack2(s0.f[3], s1.f[0]);
            P[5]  = pack2(s1.f[1], s1.f[2]);
            P[7]  = pack2(s1.f[3], s2.f[0]);
            P[9]  = pack2(s2.f[1], s2.f[2]);
            #pragma unroll
            for (int dx = 0; dx < ND; dx++) {
                acc2[dx][0] = ffma2(f0.u[0], P[dx],     acc2[dx][0]);
                acc2[dx][1] = ffma2(f0.u[1], P[dx + 2], acc2[dx][1]);
            }
        }
        buf = (buf == NSTAGE - 1) ? 0 : buf + 1;
    }

    // ---- epilogue: scale by 1/C and store ----
    const float scale = 1.0f / (float)NC;
    float* obase = out + (((size_t)b * (ND*ND) + (size_t)dy * ND) * NH + (h0 + row)) * NW
                       + (w0 + x0);
    #pragma unroll
    for (int dx = 0; dx < ND; dx++) {
        float l0, h1, l2, h3;
        unpack2(acc2[dx][0], l0, h1);
        unpack2(acc2[dx][1], l2, h3);
        float4 v = make_float4(l0*scale, h1*scale, l2*scale, h3*scale);
        *(float4*)(obase + (size_t)dx * HW) = v;
    }
}

extern "C" void kernel_launch(void* const* d_in, const int* in_sizes, int n_in,
                              void* d_out, int out_size)
{
    const float* tenFirst  = (const float*)d_in[0];
    const float* tenSecond = (const float*)d_in[1];
    float* out = (float*)d_out;

    dim3 grid(NW / TW, NH / TH, NB);   // 10 x 24 x 4 = 960 blocks
    dim3 block(NTHR);
    corr_kernel<<<grid, block>>>(tenFirst, tenSecond, out);
}

// round 7
// speedup vs baseline: 1.3825x; 1.1659x over previous
#include <cuda_runtime.h>
#include <cstddef>

#define MD 4
#define ND 9            // 2*MD+1
#define NB 4
#define NC 64
#define NH 192
#define NW 320
#define HW (NH*NW)

#define TW 16
#define TH 8
#define NTHR 288        // 4 xgroups * 8 rows * 9 dy  (warp = 4xg x 8rows, dy = warp id)
#define CCH 4           // channels per chunk
#define NCHUNK (NC/CCH) // 16
#define NSTAGE 3

#define SCOLS 24        // TW + 2*MD data cols
#define SPITCH 48       // pitch ≡ 16 (mod 32) -> conflict-free across row pairs
#define SROWS 16        // TH + 2*MD
#define FPITCH 16
#define S_CH_STRIDE (SROWS*SPITCH)      // 768 floats
#define S_BUF_STRIDE (CCH*S_CH_STRIDE)  // 3072 floats
#define F_CH_STRIDE (TH*FPITCH)         // 128 floats
#define F_BUF_STRIDE (CCH*F_CH_STRIDE)  // 512 floats

__device__ __forceinline__ void cp_async16(float* smem, const float* gmem) {
    unsigned saddr = (unsigned)__cvta_generic_to_shared(smem);
    asm volatile("cp.async.cg.shared.global [%0], [%1], 16;\n" :: "r"(saddr), "l"(gmem));
}
__device__ __forceinline__ void cp_commit() { asm volatile("cp.async.commit_group;\n" ::: "memory"); }
__device__ __forceinline__ void cp_wait0()  { asm volatile("cp.async.wait_group 0;\n" ::: "memory"); }
__device__ __forceinline__ void cp_wait1()  { asm volatile("cp.async.wait_group 1;\n" ::: "memory"); }

// packed f32x2 helpers (sm_103a)
__device__ __forceinline__ unsigned long long ffma2(unsigned long long a,
                                                    unsigned long long b,
                                                    unsigned long long c) {
    unsigned long long d;
    asm("fma.rn.f32x2 %0, %1, %2, %3;" : "=l"(d) : "l"(a), "l"(b), "l"(c));
    return d;
}
__device__ __forceinline__ unsigned long long pack2(float lo, float hi) {
    unsigned long long r;
    asm("mov.b64 %0, {%1, %2};" : "=l"(r)
        : "r"(__float_as_uint(lo)), "r"(__float_as_uint(hi)));
    return r;
}
__device__ __forceinline__ void unpack2(unsigned long long v, float& lo, float& hi) {
    unsigned a, b;
    asm("mov.b64 {%0, %1}, %2;" : "=r"(a), "=r"(b) : "l"(v));
    lo = __uint_as_float(a); hi = __uint_as_float(b);
}

union F4U {
    float4 v;
    unsigned long long u[2];
    float f[4];
};

__global__ void __launch_bounds__(NTHR, 2)
corr_kernel(const float* __restrict__ F, const float* __restrict__ S, float* __restrict__ out)
{
    __shared__ __align__(16) float sS[NSTAGE*S_BUF_STRIDE];   // 36.9 KB
    __shared__ __align__(16) float sF[NSTAGE*F_BUF_STRIDE];   //  6.0 KB

    const int tid = threadIdx.x;
    const int w0  = blockIdx.x * TW;
    const int h0  = blockIdx.y * TH;
    const int b   = blockIdx.z;

    const int xg  = tid & 3;
    const int row = (tid >> 2) & 7;
    const int dy  = tid >> 5;        // 0..8 (= warp id)
    const int x0  = xg * 4;

    // ---- per-thread cp.async assignments (block-constant) ----
    // S tile: 4ch * 16rows * 6 float4 = 384 items; <=2 per thread
    int          s_sofs[2];
    const float* s_gptr[2];
    bool         s_valid[2];
    bool         s_act[2];
    const float* Sbase = S + (size_t)b * NC * HW;
    #pragma unroll
    for (int t = 0; t < 2; t++) {
        int i    = tid + NTHR * t;
        bool act = (i < 384);
        s_act[t] = act;
        int ii  = act ? i : 0;
        int ch  = ii / 96;
        int rem = ii % 96;
        int r   = rem / 6;
        int j   = rem % 6;
        int gr  = h0 + r - MD;
        int gc  = w0 - MD + 4*j;
        bool v  = (gr >= 0) && (gr < NH) && (gc >= 0) && (gc < NW);
        s_valid[t] = v;
        s_sofs[t]  = ch * S_CH_STRIDE + r * SPITCH + 4*j;
        s_gptr[t]  = Sbase + (size_t)ch * HW + (v ? (gr*NW + gc) : 0);
    }
    // F tile: 4ch * 8rows * 4 float4 = 128 items (tid < 128), always in-range
    const bool f_active = (tid < 128);
    int f_sofs;
    const float* f_gptr;
    {
        int ch = tid >> 5;
        int r  = (tid >> 2) & 7;
        int j  = tid & 3;
        f_sofs = ch * F_CH_STRIDE + r * FPITCH + 4*j;
        f_gptr = F + (size_t)b * NC * HW + (size_t)ch * HW + (h0 + r) * NW + (w0 + 4*j);
    }

    // zero-fill OOB padding slots once in every stage (validity identical per chunk)
    #pragma unroll
    for (int t = 0; t < 2; t++) {
        if (s_act[t] && !s_valid[t]) {
            float4 z = make_float4(0.f, 0.f, 0.f, 0.f);
            #pragma unroll
            for (int st = 0; st < NSTAGE; st++)
                *(float4*)&sS[st*S_BUF_STRIDE + s_sofs[t]] = z;
        }
    }

    auto issue = [&](int k) {
        const int stg = k % NSTAGE;
        const size_t cofs = (size_t)k * CCH * HW;
        #pragma unroll
        for (int t = 0; t < 2; t++)
            if (s_act[t] && s_valid[t])
                cp_async16(&sS[stg*S_BUF_STRIDE + s_sofs[t]], s_gptr[t] + cofs);
        if (f_active)
            cp_async16(&sF[stg*F_BUF_STRIDE + f_sofs], f_gptr + cofs);
        cp_commit();
    };

    // prologue: chunks 0 and 1 in flight
    issue(0);
    issue(1);

    // packed accumulators: acc2[dx][q] holds pixels (2q, 2q+1)
    unsigned long long acc2[ND][2];
    #pragma unroll
    for (int dx = 0; dx < ND; dx++) { acc2[dx][0] = 0ull; acc2[dx][1] = 0ull; }

    const int srow_ofs = (row + dy) * SPITCH + x0;
    const int frow_ofs = row * FPITCH + x0;

    int buf = 0;
    #pragma unroll 1
    for (int k = 0; k < NCHUNK; k++) {
        if (k < NCHUNK - 1) cp_wait1(); else cp_wait0();
        __syncthreads();   // chunk-k data visible; all warps done with the buf being refilled

        if (k + 2 < NCHUNK) issue(k + 2);

        const float* sSb = &sS[buf*S_BUF_STRIDE + srow_ofs];
        const float* sFb = &sF[buf*F_BUF_STRIDE + frow_ofs];
        #pragma unroll
        for (int cc = 0; cc < CCH; cc++) {
            F4U s0, s1, s2, f0;
            s0.v = *(const float4*)(sSb + cc*S_CH_STRIDE);
            s1.v = *(const float4*)(sSb + cc*S_CH_STRIDE + 4);
            s2.v = *(const float4*)(sSb + cc*S_CH_STRIDE + 8);
            f0.v = *(const float4*)(sFb + cc*F_CH_STRIDE);
            // P[i] = (sv[i], sv[i+1]), i = 0..10
            unsigned long long P[11];
            P[0]  = s0.u[0];  P[2]  = s0.u[1];
            P[4]  = s1.u[0];  P[6]  = s1.u[1];
            P[8]  = s2.u[0];  P[10] = s2.u[1];
            P[1]  = pack2(s0.f[1], s0.f[2]);
            P[3]  = pack2(s0.f[3], s1.f[0]);
            P[5]  = pack2(s1.f[1], s1.f[2]);
            P[7]  = pack2(s1.f[3], s2.f[0]);
            P[9]  = pack2(s2.f[1], s2.f[2]);
            #pragma unroll
            for (int dx = 0; dx < ND; dx++) {
                acc2[dx][0] = ffma2(f0.u[0], P[dx],     acc2[dx][0]);
                acc2[dx][1] = ffma2(f0.u[1], P[dx + 2], acc2[dx][1]);
            }
        }
        buf = (buf == NSTAGE - 1) ? 0 : buf + 1;
    }

    // ---- epilogue: scale by 1/C and store ----
    const float scale = 1.0f / (float)NC;
    float* obase = out + (((size_t)b * (ND*ND) + (size_t)dy * ND) * NH + (h0 + row)) * NW
                       + (w0 + x0);
    #pragma unroll
    for (int dx = 0; dx < ND; dx++) {
        float l0, h1, l2, h3;
        unpack2(acc2[dx][0], l0, h1);
        unpack2(acc2[dx][1], l2, h3);
        float4 v = make_float4(l0*scale, h1*scale, l2*scale, h3*scale);
        *(float4*)(obase + (size_t)dx * HW) = v;
    }
}

extern "C" void kernel_launch(void* const* d_in, const int* in_sizes, int n_in,
                              void* d_out, int out_size)
{
    const float* tenFirst  = (const float*)d_in[0];
    const float* tenSecond = (const float*)d_in[1];
    float* out = (float*)d_out;

    dim3 grid(NW / TW, NH / TH, NB);   // 20 x 24 x 4 = 1920 blocks
    dim3 block(NTHR);
    corr_kernel<<<grid, block>>>(tenFirst, tenSecond, out);
}

// round 9
// speedup vs baseline: 1.4354x; 1.0383x over previous
#include <cuda_runtime.h>
#include <cstddef>

#define MD 4
#define ND 9            // 2*MD+1
#define NB 4
#define NC 64
#define NH 192
#define NW 320
#define HW (NH*NW)

#define TW 16
#define TH 8
#define NTHR 288        // 9 warps: warps 0..7 = (4xg x 8dy) for row w; warp 8 = dy=8 tail
#define CCH 8           // channels per chunk
#define NCHUNK (NC/CCH) // 8
#define NSTAGE 3

#define SCOLS 24        // TW + 2*MD data cols
#define SPITCH 48       // ≡16 mod 32 -> conflict-free LDS.128 phases
#define SROWS 16        // TH + 2*MD
#define FPITCH 16
#define S_CH_STRIDE (SROWS*SPITCH)      // 768 floats
#define S_BUF_STRIDE (CCH*S_CH_STRIDE)  // 6144 floats / stage
#define F_CH_STRIDE (TH*FPITCH)         // 128 floats
#define F_BUF_STRIDE (CCH*F_CH_STRIDE)  // 1024 floats / stage

#define SMEM_FLOATS (NSTAGE*(S_BUF_STRIDE + F_BUF_STRIDE))   // 21504 floats
#define SMEM_BYTES  (SMEM_FLOATS * 4)                        // 86016 B

__device__ __forceinline__ void cp_async16(float* smem, const float* gmem) {
    unsigned saddr = (unsigned)__cvta_generic_to_shared(smem);
    asm volatile("cp.async.cg.shared.global [%0], [%1], 16;\n" :: "r"(saddr), "l"(gmem));
}
__device__ __forceinline__ void cp_commit() { asm volatile("cp.async.commit_group;\n" ::: "memory"); }
__device__ __forceinline__ void cp_wait0()  { asm volatile("cp.async.wait_group 0;\n" ::: "memory"); }
__device__ __forceinline__ void cp_wait1()  { asm volatile("cp.async.wait_group 1;\n" ::: "memory"); }

// packed f32x2 helpers (sm_103a)
__device__ __forceinline__ unsigned long long ffma2(unsigned long long a,
                                                    unsigned long long b,
                                                    unsigned long long c) {
    unsigned long long d;
    asm("fma.rn.f32x2 %0, %1, %2, %3;" : "=l"(d) : "l"(a), "l"(b), "l"(c));
    return d;
}
__device__ __forceinline__ unsigned long long pack2(float lo, float hi) {
    unsigned long long r;
    asm("mov.b64 %0, {%1, %2};" : "=l"(r)
        : "r"(__float_as_uint(lo)), "r"(__float_as_uint(hi)));
    return r;
}
__device__ __forceinline__ void unpack2(unsigned long long v, float& lo, float& hi) {
    unsigned a, b;
    asm("mov.b64 {%0, %1}, %2;" : "=r"(a), "=r"(b) : "l"(v));
    lo = __uint_as_float(a); hi = __uint_as_float(b);
}

union F4U {
    float4 v;
    unsigned long long u[2];
    float f[4];
};

__global__ void __launch_bounds__(NTHR, 2)
corr_kernel(const float* __restrict__ F, const float* __restrict__ S, float* __restrict__ out)
{
    extern __shared__ __align__(16) float smem[];
    float* sS = smem;                          // NSTAGE * 6144 floats
    float* sF = smem + NSTAGE * S_BUF_STRIDE;  // NSTAGE * 1024 floats

    const int tid  = threadIdx.x;
    const int lane = tid & 31;
    const int wid  = tid >> 5;
    const int w0   = blockIdx.x * TW;
    const int h0   = blockIdx.y * TH;
    const int b    = blockIdx.z;

    // warp layout: warps 0..7 -> row=wid, lanes = (xg:2b, dy:3b); F reads broadcast
    //              warp 8     -> dy=8,    lanes = (xg:2b, row:3b)
    const int xg = lane & 3;
    const int x0 = xg * 4;
    int row, dy;
    if (wid < 8) { row = wid;       dy = lane >> 2; }
    else         { row = lane >> 2; dy = 8;         }

    // ---- per-thread cp.async assignments (block-constant) ----
    // S tile: 8ch * 16rows * 6 float4 = 768 items; <=3 per thread
    int          s_sofs[3];
    const float* s_gptr[3];
    bool         s_valid[3];
    bool         s_act[3];
    const float* Sbase = S + (size_t)b * NC * HW;
    #pragma unroll
    for (int t = 0; t < 3; t++) {
        int i    = tid + NTHR * t;
        bool act = (i < 768);
        s_act[t] = act;
        int ii  = act ? i : 0;
        int ch  = ii / 96;
        int rem = ii % 96;
        int r   = rem / 6;
        int j   = rem % 6;
        int gr  = h0 + r - MD;
        int gc  = w0 - MD + 4*j;
        bool v  = (gr >= 0) && (gr < NH) && (gc >= 0) && (gc < NW);
        s_valid[t] = v;
        s_sofs[t]  = ch * S_CH_STRIDE + r * SPITCH + 4*j;
        s_gptr[t]  = Sbase + (size_t)ch * HW + (v ? (gr*NW + gc) : 0);
    }
    // F tile: 8ch * 8rows * 4 float4 = 256 items (tid < 256), always in-range
    const bool f_active = (tid < 256);
    int f_sofs;
    const float* f_gptr;
    {
        int ch = tid >> 5;
        int r  = (tid >> 2) & 7;
        int j  = tid & 3;
        f_sofs = ch * F_CH_STRIDE + r * FPITCH + 4*j;
        f_gptr = F + (size_t)b * NC * HW + (size_t)ch * HW + (h0 + r) * NW + (w0 + 4*j);
    }

    // zero-fill OOB padding slots once in every stage (validity identical per chunk)
    #pragma unroll
    for (int t = 0; t < 3; t++) {
        if (s_act[t] && !s_valid[t]) {
            float4 z = make_float4(0.f, 0.f, 0.f, 0.f);
            #pragma unroll
            for (int st = 0; st < NSTAGE; st++)
                *(float4*)&sS[st*S_BUF_STRIDE + s_sofs[t]] = z;
        }
    }

    auto issue = [&](int k) {
        const int stg = k % NSTAGE;
        const size_t cofs = (size_t)k * CCH * HW;
        #pragma unroll
        for (int t = 0; t < 3; t++)
            if (s_act[t] && s_valid[t])
                cp_async16(&sS[stg*S_BUF_STRIDE + s_sofs[t]], s_gptr[t] + cofs);
        if (f_active)
            cp_async16(&sF[stg*F_BUF_STRIDE + f_sofs], f_gptr + cofs);
        cp_commit();
    };

    // prologue: chunks 0 and 1 in flight
    issue(0);
    issue(1);

    // packed accumulators: acc2[dx][q] holds pixels (2q, 2q+1)
    unsigned long long acc2[ND][2];
    #pragma unroll
    for (int dx = 0; dx < ND; dx++) { acc2[dx][0] = 0ull; acc2[dx][1] = 0ull; }

    const int srow_ofs = (row + dy) * SPITCH + x0;
    const int frow_ofs = row * FPITCH + x0;

    int buf = 0;
    #pragma unroll 1
    for (int k = 0; k < NCHUNK; k++) {
        if (k < NCHUNK - 1) cp_wait1(); else cp_wait0();
        __syncthreads();   // chunk-k data visible; all warps done with buf (k+2)%NSTAGE

        if (k + 2 < NCHUNK) issue(k + 2);

        const float* sSb = &sS[buf*S_BUF_STRIDE + srow_ofs];
        const float* sFb = &sF[buf*F_BUF_STRIDE + frow_ofs];
        #pragma unroll 4
        for (int cc = 0; cc < CCH; cc++) {
            F4U s0, s1, s2, f0;
            s0.v = *(const float4*)(sSb + cc*S_CH_STRIDE);
            s1.v = *(const float4*)(sSb + cc*S_CH_STRIDE + 4);
            s2.v = *(const float4*)(sSb + cc*S_CH_STRIDE + 8);
            f0.v = *(const float4*)(sFb + cc*F_CH_STRIDE);   // broadcast across dy lanes
            // P[i] = (sv[i], sv[i+1]), i = 0..10
            unsigned long long P[11];
            P[0]  = s0.u[0];  P[2]  = s0.u[1];
            P[4]  = s1.u[0];  P[6]  = s1.u[1];
            P[8]  = s2.u[0];  P[10] = s2.u[1];
            P[1]  = pack2(s0.f[1], s0.f[2]);
            P[3]  = pack2(s0.f[3], s1.f[0]);
            P[5]  = pack2(s1.f[1], s1.f[2]);
            P[7]  = pack2(s1.f[3], s2.f[0]);
            P[9]  = pack2(s2.f[1], s2.f[2]);
            #pragma unroll
            for (int dx = 0; dx < ND; dx++) {
                acc2[dx][0] = ffma2(f0.u[0], P[dx],     acc2[dx][0]);
                acc2[dx][1] = ffma2(f0.u[1], P[dx + 2], acc2[dx][1]);
            }
        }
        buf = (buf == NSTAGE - 1) ? 0 : buf + 1;
    }

    // ---- epilogue: scale by 1/C and store ----
    const float scale = 1.0f / (float)NC;
    float* obase = out + (((size_t)b * (ND*ND) + (size_t)dy * ND) * NH + (h0 + row)) * NW
                       + (w0 + x0);
    #pragma unroll
    for (int dx = 0; dx < ND; dx++) {
        float l0, h1, l2, h3;
        unpack2(acc2[dx][0], l0, h1);
        unpack2(acc2[dx][1], l2, h3);
        float4 v = make_float4(l0*scale, h1*scale, l2*scale, h3*scale);
        *(float4*)(obase + (size_t)dx * HW) = v;
    }
}

extern "C" void kernel_launch(void* const* d_in, const int* in_sizes, int n_in,
                              void* d_out, int out_size)
{
    const float* tenFirst  = (const float*)d_in[0];
    const float* tenSecond = (const float*)d_in[1];
    float* out = (float*)d_out;

    cudaFuncSetAttribute(corr_kernel,
                         cudaFuncAttributeMaxDynamicSharedMemorySize, SMEM_BYTES);

    dim3 grid(NW / TW, NH / TH, NB);   // 20 x 24 x 4 = 1920 blocks
    dim3 block(NTHR);
    corr_kernel<<<grid, block, SMEM_BYTES>>>(tenFirst, tenSecond, out);
}

// round 14
// speedup vs baseline: 1.4603x; 1.0173x over previous
#include <cuda_runtime.h>
#include <cstddef>

#define MD 4
#define ND 9            // 2*MD+1
#define NB 4
#define NC 64
#define NH 192
#define NW 320
#define HW (NH*NW)

#define TW 16
#define TH 8
#define NTHR 288        // 9 warps: warps 0..7 = (4xg x 8dy) row-warps; warp 8 = dy=8 tail
#define NWARP 9
#define CCH 8           // channels per chunk
#define NCHUNK (NC/CCH) // 8
#define NSTAGE 3

#define SCOLS 24        // TW + 2*MD data cols
#define SPITCH 48       // ≡16 mod 32 -> conflict-free LDS.128 phases
#define SROWS 16        // TH + 2*MD
#define FPITCH 16
#define S_CH_STRIDE (SROWS*SPITCH)      // 768 floats
#define S_BUF_STRIDE (CCH*S_CH_STRIDE)  // 6144 floats / stage
#define F_CH_STRIDE (TH*FPITCH)         // 128 floats
#define F_BUF_STRIDE (CCH*F_CH_STRIDE)  // 1024 floats / stage

#define SMEM_FLOATS (NSTAGE*(S_BUF_STRIDE + F_BUF_STRIDE))   // 21504 floats
#define SMEM_BYTES  (SMEM_FLOATS * 4)                        // 86016 B

__device__ __forceinline__ void cp_async16(float* smem, const float* gmem) {
    unsigned saddr = (unsigned)__cvta_generic_to_shared(smem);
    asm volatile("cp.async.cg.shared.global [%0], [%1], 16;\n" :: "r"(saddr), "l"(gmem));
}

// ---- mbarrier helpers ----
__device__ __forceinline__ void mbar_init(unsigned addr, unsigned count) {
    asm volatile("mbarrier.init.shared.b64 [%0], %1;" :: "r"(addr), "r"(count) : "memory");
}
__device__ __forceinline__ void mbar_arrive(unsigned addr) {
    asm volatile("mbarrier.arrive.shared.b64 _, [%0];" :: "r"(addr) : "memory");
}
// REAL arrive (counts against init count) when ALL prior cp.asyncs of this
// thread complete. The non-.noinc form is +1/-1 = net zero -> deadlock (R10 bug).
__device__ __forceinline__ void cp_async_mbar_arrive_noinc(unsigned addr) {
    asm volatile("cp.async.mbarrier.arrive.noinc.shared.b64 [%0];" :: "r"(addr) : "memory");
}
__device__ __forceinline__ void mbar_wait(unsigned addr, unsigned phase) {
    asm volatile(
        "{\n\t"
        ".reg .pred p;\n\t"
        "LAB_WAIT_%=:\n\t"
        "mbarrier.try_wait.parity.acquire.cta.shared::cta.b64 p, [%0], %1, 0x989680;\n\t"
        "@!p bra LAB_WAIT_%=;\n\t"
        "}"
        :: "r"(addr), "r"(phase) : "memory");
}

// packed f32x2 helpers (sm_103a)
__device__ __forceinline__ unsigned long long ffma2(unsigned long long a,
                                                    unsigned long long b,
                                                    unsigned long long c) {
    unsigned long long d;
    asm("fma.rn.f32x2 %0, %1, %2, %3;" : "=l"(d) : "l"(a), "l"(b), "l"(c));
    return d;
}
__device__ __forceinline__ unsigned long long pack2(float lo, float hi) {
    unsigned long long r;
    asm("mov.b64 %0, {%1, %2};" : "=l"(r)
        : "r"(__float_as_uint(lo)), "r"(__float_as_uint(hi)));
    return r;
}
__device__ __forceinline__ void unpack2(unsigned long long v, float& lo, float& hi) {
    unsigned a, b;
    asm("mov.b64 {%0, %1}, %2;" : "=r"(a), "=r"(b) : "l"(v));
    lo = __uint_as_float(a); hi = __uint_as_float(b);
}

union F4U {
    float4 v;
    unsigned long long u[2];
    float f[4];
};

__global__ void __launch_bounds__(NTHR, 2)
corr_kernel(const float* __restrict__ F, const float* __restrict__ S, float* __restrict__ out)
{
    extern __shared__ __align__(16) float smem[];
    float* sS = smem;                          // NSTAGE * 6144 floats
    float* sF = smem + NSTAGE * S_BUF_STRIDE;  // NSTAGE * 1024 floats
    __shared__ __align__(8) unsigned long long smem_mbar[2*NSTAGE]; // full[0..2], empty[0..2]

    const unsigned mbar_base = (unsigned)__cvta_generic_to_shared(smem_mbar);
    // full[s] = mbar_base + 8*s ; empty[s] = mbar_base + 8*(NSTAGE+s)

    const int tid  = threadIdx.x;
    const int lane = tid & 31;
    const int wid  = tid >> 5;
    const int w0   = blockIdx.x * TW;
    const int h0   = blockIdx.y * TH;
    const int b    = blockIdx.z;

    // warp layout: warps 0..7 -> row=wid, lanes = (xg:2b, dy:3b); F reads broadcast
    //              warp 8     -> dy=8,    lanes = (xg:2b, row:3b)
    const int xg = lane & 3;
    const int x0 = xg * 4;
    int row, dy;
    if (wid < 8) { row = wid;       dy = lane >> 2; }
    else         { row = lane >> 2; dy = 8;         }

    // ---- per-thread cp.async assignments (block-constant) ----
    // S tile: 8ch * 16rows * 6 float4 = 768 items; <=3 per thread
    int          s_sofs[3];
    const float* s_gptr[3];
    bool         s_valid[3];
    bool         s_act[3];
    const float* Sbase = S + (size_t)b * NC * HW;
    #pragma unroll
    for (int t = 0; t < 3; t++) {
        int i    = tid + NTHR * t;
        bool act = (i < 768);
        s_act[t] = act;
        int ii  = act ? i : 0;
        int ch  = ii / 96;
        int rem = ii % 96;
        int r   = rem / 6;
        int j   = rem % 6;
        int gr  = h0 + r - MD;
        int gc  = w0 - MD + 4*j;
        bool v  = (gr >= 0) && (gr < NH) && (gc >= 0) && (gc < NW);
        s_valid[t] = v;
        s_sofs[t]  = ch * S_CH_STRIDE + r * SPITCH + 4*j;
        s_gptr[t]  = Sbase + (size_t)ch * HW + (v ? (gr*NW + gc) : 0);
    }
    // F tile: 8ch * 8rows * 4 float4 = 256 items (tid < 256), always in-range
    const bool f_active = (tid < 256);
    int f_sofs;
    const float* f_gptr;
    {
        int ch = tid >> 5;
        int r  = (tid >> 2) & 7;
        int j  = tid & 3;
        f_sofs = ch * F_CH_STRIDE + r * FPITCH + 4*j;
        f_gptr = F + (size_t)b * NC * HW + (size_t)ch * HW + (h0 + r) * NW + (w0 + 4*j);
    }

    // ---- one-time init: mbarriers + OOB pad zero-fill, then single barrier ----
    if (tid == 0) {
        #pragma unroll
        for (int s = 0; s < NSTAGE; s++) {
            mbar_init(mbar_base + 8*s, NTHR);                 // full[s]
            mbar_init(mbar_base + 8*(NSTAGE + s), NWARP);     // empty[s]
        }
    }
    #pragma unroll
    for (int t = 0; t < 3; t++) {
        if (s_act[t] && !s_valid[t]) {
            float4 z = make_float4(0.f, 0.f, 0.f, 0.f);
            #pragma unroll
            for (int st = 0; st < NSTAGE; st++)
                *(float4*)&sS[st*S_BUF_STRIDE + s_sofs[t]] = z;
        }
    }
    __syncthreads();

    auto issue = [&](int k) {
        const int stg = k % NSTAGE;
        const size_t cofs = (size_t)k * CCH * HW;
        #pragma unroll
        for (int t = 0; t < 3; t++)
            if (s_act[t] && s_valid[t])
                cp_async16(&sS[stg*S_BUF_STRIDE + s_sofs[t]], s_gptr[t] + cofs);
        if (f_active)
            cp_async16(&sF[stg*F_BUF_STRIDE + f_sofs], f_gptr + cofs);
        cp_async_mbar_arrive_noinc(mbar_base + 8*stg);   // real arrive on completion
    };

    // prologue: chunks 0 and 1 in flight (stages 0,1 fresh — no empty wait)
    issue(0);
    issue(1);

    // packed accumulators: acc2[dx][q] holds pixels (2q, 2q+1)
    unsigned long long acc2[ND][2];
    #pragma unroll
    for (int dx = 0; dx < ND; dx++) { acc2[dx][0] = 0ull; acc2[dx][1] = 0ull; }

    const int srow_ofs = (row + dy) * SPITCH + x0;
    const int frow_ofs = row * FPITCH + x0;

    #pragma unroll 1
    for (int k = 0; k < NCHUNK; k++) {
        // prefetch chunk k+2 into stage (k+2)%NSTAGE
        const int kp = k + 2;
        if (kp < NCHUNK) {
            const int sp = kp % NSTAGE;
            if (kp >= NSTAGE)   // recycling: wait until all 9 warps released it
                mbar_wait(mbar_base + 8*(NSTAGE + sp), ((unsigned)(kp/NSTAGE) - 1u) & 1u);
            issue(kp);
        }

        // consume chunk k
        const int s = k % NSTAGE;
        mbar_wait(mbar_base + 8*s, (unsigned)(k/NSTAGE) & 1u);

        const float* sSb = &sS[s*S_BUF_STRIDE + srow_ofs];
        const float* sFb = &sF[s*F_BUF_STRIDE + frow_ofs];
        #pragma unroll 4
        for (int cc = 0; cc < CCH; cc++) {
            F4U s0, s1, s2, f0;
            s0.v = *(const float4*)(sSb + cc*S_CH_STRIDE);
            s1.v = *(const float4*)(sSb + cc*S_CH_STRIDE + 4);
            s2.v = *(const float4*)(sSb + cc*S_CH_STRIDE + 8);
            f0.v = *(const float4*)(sFb + cc*F_CH_STRIDE);   // broadcast across dy lanes
            // P[i] = (sv[i], sv[i+1]), i = 0..10
            unsigned long long P[11];
            P[0]  = s0.u[0];  P[2]  = s0.u[1];
            P[4]  = s1.u[0];  P[6]  = s1.u[1];
            P[8]  = s2.u[0];  P[10] = s2.u[1];
            P[1]  = pack2(s0.f[1], s0.f[2]);
            P[3]  = pack2(s0.f[3], s1.f[0]);
            P[5]  = pack2(s1.f[1], s1.f[2]);
            P[7]  = pack2(s1.f[3], s2.f[0]);
            P[9]  = pack2(s2.f[1], s2.f[2]);
            #pragma unroll
            for (int dx = 0; dx < ND; dx++) {
                acc2[dx][0] = ffma2(f0.u[0], P[dx],     acc2[dx][0]);
                acc2[dx][1] = ffma2(f0.u[1], P[dx + 2], acc2[dx][1]);
            }
        }

        // this warp is done reading stage s (FFMA2s consumed every loaded value)
        __syncwarp();
        if (lane == 0) mbar_arrive(mbar_base + 8*(NSTAGE + s));
    }

    // ---- epilogue: scale by 1/C and store ----
    const float scale = 1.0f / (float)NC;
    float* obase = out + (((size_t)b * (ND*ND) + (size_t)dy * ND) * NH + (h0 + row)) * NW
                       + (w0 + x0);
    #pragma unroll
    for (int dx = 0; dx < ND; dx++) {
        float l0, h1, l2, h3;
        unpack2(acc2[dx][0], l0, h1);
        unpack2(acc2[dx][1], l2, h3);
        float4 v = make_float4(l0*scale, h1*scale, l2*scale, h3*scale);
        *(float4*)(obase + (size_t)dx * HW) = v;
    }
}

extern "C" void kernel_launch(void* const* d_in, const int* in_sizes, int n_in,
                              void* d_out, int out_size)
{
    const float* tenFirst  = (const float*)d_in[0];
    const float* tenSecond = (const float*)d_in[1];
    float* out = (float*)d_out;

    cudaFuncSetAttribute(corr_kernel,
                         cudaFuncAttributeMaxDynamicSharedMemorySize, SMEM_BYTES);

    dim3 grid(NW / TW, NH / TH, NB);   // 20 x 24 x 4 = 1920 blocks
    dim3 block(NTHR);
    corr_kernel<<<grid, block, SMEM_BYTES>>>(tenFirst, tenSecond, out);
}

// round 17
// speedup vs baseline: 1.5195x; 1.0405x over previous
#include <cuda_runtime.h>
#include <cstddef>

#define MD 4
#define ND 9            // 2*MD+1
#define NB 4
#define NC 64
#define NH 192
#define NW 320
#define HW (NH*NW)

#define TW 16
#define TH 8
#define NTHR 288        // 9 warps: warps 0..7 = (4xg x 8dy) row-warps; warp 8 = dy=8 tail
#define NWARP 9
#define CCH 4           // channels per chunk
#define NCHUNK (NC/CCH) // 16
#define NSTAGE 5
#define PDIST 2         // prefetch distance (chunks)

#define SCOLS 24        // TW + 2*MD data cols
#define SPITCH 48       // ≡16 mod 32 -> conflict-free LDS.128 phases
#define SROWS 16        // TH + 2*MD
#define FPITCH 16
#define S_CH_STRIDE (SROWS*SPITCH)      // 768 floats
#define S_BUF_STRIDE (CCH*S_CH_STRIDE)  // 3072 floats / stage
#define F_CH_STRIDE (TH*FPITCH)         // 128 floats
#define F_BUF_STRIDE (CCH*F_CH_STRIDE)  // 512 floats / stage

#define SMEM_FLOATS (NSTAGE*(S_BUF_STRIDE + F_BUF_STRIDE))   // 17920 floats
#define SMEM_BYTES  (SMEM_FLOATS * 4)                        // 71680 B -> 3 blocks/SM

__device__ __forceinline__ void cp_async16(float* smem, const float* gmem) {
    unsigned saddr = (unsigned)__cvta_generic_to_shared(smem);
    asm volatile("cp.async.cg.shared.global [%0], [%1], 16;\n" :: "r"(saddr), "l"(gmem));
}

// ---- mbarrier helpers ----
__device__ __forceinline__ void mbar_init(unsigned addr, unsigned count) {
    asm volatile("mbarrier.init.shared.b64 [%0], %1;" :: "r"(addr), "r"(count) : "memory");
}
__device__ __forceinline__ void mbar_arrive(unsigned addr) {
    asm volatile("mbarrier.arrive.shared.b64 _, [%0];" :: "r"(addr) : "memory");
}
// REAL arrive (counts against init count) when ALL prior cp.asyncs of this
// thread complete. (non-.noinc form is +1/-1 = net zero -> deadlock)
__device__ __forceinline__ void cp_async_mbar_arrive_noinc(unsigned addr) {
    asm volatile("cp.async.mbarrier.arrive.noinc.shared.b64 [%0];" :: "r"(addr) : "memory");
}
__device__ __forceinline__ void mbar_wait(unsigned addr, unsigned phase) {
    asm volatile(
        "{\n\t"
        ".reg .pred p;\n\t"
        "LAB_WAIT_%=:\n\t"
        "mbarrier.try_wait.parity.acquire.cta.shared::cta.b64 p, [%0], %1, 0x989680;\n\t"
        "@!p bra LAB_WAIT_%=;\n\t"
        "}"
        :: "r"(addr), "r"(phase) : "memory");
}

// packed f32x2 helpers (sm_103a)
__device__ __forceinline__ unsigned long long ffma2(unsigned long long a,
                                                    unsigned long long b,
                                                    unsigned long long c) {
    unsigned long long d;
    asm("fma.rn.f32x2 %0, %1, %2, %3;" : "=l"(d) : "l"(a), "l"(b), "l"(c));
    return d;
}
__device__ __forceinline__ unsigned long long pack2(float lo, float hi) {
    unsigned long long r;
    asm("mov.b64 %0, {%1, %2};" : "=l"(r)
        : "r"(__float_as_uint(lo)), "r"(__float_as_uint(hi)));
    return r;
}
__device__ __forceinline__ void unpack2(unsigned long long v, float& lo, float& hi) {
    unsigned a, b;
    asm("mov.b64 {%0, %1}, %2;" : "=r"(a), "=r"(b) : "l"(v));
    lo = __uint_as_float(a); hi = __uint_as_float(b);
}

union F4U {
    float4 v;
    unsigned long long u[2];
    float f[4];
};

__global__ void __launch_bounds__(NTHR, 3)
corr_kernel(const float* __restrict__ F, const float* __restrict__ S, float* __restrict__ out)
{
    extern __shared__ __align__(16) float smem[];
    float* sS = smem;                          // NSTAGE * 3072 floats
    float* sF = smem + NSTAGE * S_BUF_STRIDE;  // NSTAGE * 512 floats
    __shared__ __align__(8) unsigned long long smem_mbar[2*NSTAGE]; // full[0..4], empty[0..4]

    const unsigned mbar_base = (unsigned)__cvta_generic_to_shared(smem_mbar);
    // full[s] = mbar_base + 8*s ; empty[s] = mbar_base + 8*(NSTAGE+s)

    const int tid  = threadIdx.x;
    const int lane = tid & 31;
    const int wid  = tid >> 5;
    const int w0   = blockIdx.x * TW;
    const int h0   = blockIdx.y * TH;
    const int b    = blockIdx.z;

    // warp layout: warps 0..7 -> row=wid, lanes = (xg:2b, dy:3b); F reads broadcast
    //              warp 8     -> dy=8,    lanes = (xg:2b, row:3b)
    const int xg = lane & 3;
    const int x0 = xg * 4;
    int row, dy;
    if (wid < 8) { row = wid;       dy = lane >> 2; }
    else         { row = lane >> 2; dy = 8;         }

    // ---- per-thread cp.async assignments (block-constant) ----
    // S tile: 4ch * 16rows * 6 float4 = 384 items; slot0 = tid (always active),
    // slot1 = tid+288 (active iff tid < 96)
    const float* Sbase = S + (size_t)b * NC * HW;
    int          s_sofs[2];
    const float* s_gptr[2];
    bool         s_valid[2];
    const bool   s1_act = (tid < 96);
    #pragma unroll
    for (int t = 0; t < 2; t++) {
        int i   = (t == 0) ? tid : (tid + NTHR);
        if (t == 1 && !s1_act) i = 0;
        int ch  = i / 96;
        int rem = i % 96;
        int r   = rem / 6;
        int j   = rem % 6;
        int gr  = h0 + r - MD;
        int gc  = w0 - MD + 4*j;
        bool v  = (gr >= 0) && (gr < NH) && (gc >= 0) && (gc < NW);
        s_valid[t] = v;
        s_sofs[t]  = ch * S_CH_STRIDE + r * SPITCH + 4*j;
        s_gptr[t]  = Sbase + (size_t)ch * HW + (v ? (gr*NW + gc) : 0);
    }
    // F tile: 4ch * 8rows * 4 float4 = 128 items (tid < 128), always in-range
    const bool f_active = (tid < 128);
    int f_sofs;
    const float* f_gptr;
    {
        int ch = tid >> 5;
        int r  = (tid >> 2) & 7;
        int j  = tid & 3;
        f_sofs = ch * F_CH_STRIDE + r * FPITCH + 4*j;
        f_gptr = F + (size_t)b * NC * HW + (size_t)ch * HW + (h0 + r) * NW + (w0 + 4*j);
    }

    // ---- one-time init: mbarriers + OOB pad zero-fill, then single barrier ----
    if (tid == 0) {
        #pragma unroll
        for (int s = 0; s < NSTAGE; s++) {
            mbar_init(mbar_base + 8*s, NTHR);                 // full[s]
            mbar_init(mbar_base + 8*(NSTAGE + s), NWARP);     // empty[s]
        }
    }
    #pragma unroll
    for (int t = 0; t < 2; t++) {
        bool act = (t == 0) || s1_act;
        if (act && !s_valid[t]) {
            float4 z = make_float4(0.f, 0.f, 0.f, 0.f);
            #pragma unroll
            for (int st = 0; st < NSTAGE; st++)
                *(float4*)&sS[st*S_BUF_STRIDE + s_sofs[t]] = z;
        }
    }
    __syncthreads();

    auto issue = [&](int k, int stg) {
        const size_t cofs = (size_t)k * CCH * HW;
        if (s_valid[0])
            cp_async16(&sS[stg*S_BUF_STRIDE + s_sofs[0]], s_gptr[0] + cofs);
        if (s1_act && s_valid[1])
            cp_async16(&sS[stg*S_BUF_STRIDE + s_sofs[1]], s_gptr[1] + cofs);
        if (f_active)
            cp_async16(&sF[stg*F_BUF_STRIDE + f_sofs], f_gptr + cofs);
        cp_async_mbar_arrive_noinc(mbar_base + 8*stg);   // arrive full[stg] on completion
    };

    // prologue: chunks 0..PDIST-1 in flight (fresh stages — no empty wait)
    issue(0, 0);
    issue(1, 1);

    // packed accumulators: acc2[dx][q] holds pixels (2q, 2q+1)
    unsigned long long acc2[ND][2];
    #pragma unroll
    for (int dx = 0; dx < ND; dx++) { acc2[dx][0] = 0ull; acc2[dx][1] = 0ull; }

    const int srow_ofs = (row + dy) * SPITCH + x0;
    const int frow_ofs = row * FPITCH + x0;

    // incremental stage/parity cursors
    int cons_s = 0, cons_ph = 0;             // consumer: chunk k -> stage k%5, parity (k/5)&1
    int prod_s = PDIST, prod_ph = 0;         // producer: chunk kp=k+2 -> stage kp%5

    #pragma unroll 1
    for (int k = 0; k < NCHUNK; k++) {
        // prefetch chunk k+PDIST
        const int kp = k + PDIST;
        if (kp < NCHUNK) {
            if (kp >= NSTAGE)   // recycling: wait until all 9 warps released chunk kp-5
                mbar_wait(mbar_base + 8*(NSTAGE + prod_s), (unsigned)prod_ph);
            issue(kp, prod_s);
            if (++prod_s == NSTAGE) { prod_s = 0; if (kp >= NSTAGE) prod_ph ^= 1; }
        }

        // consume chunk k
        mbar_wait(mbar_base + 8*cons_s, (unsigned)cons_ph);

        const float* sSb = &sS[cons_s*S_BUF_STRIDE + srow_ofs];
        const float* sFb = &sF[cons_s*F_BUF_STRIDE + frow_ofs];
        #pragma unroll
        for (int cc = 0; cc < CCH; cc++) {
            F4U s0, s1, s2, f0;
            s0.v = *(const float4*)(sSb + cc*S_CH_STRIDE);
            s1.v = *(const float4*)(sSb + cc*S_CH_STRIDE + 4);
            s2.v = *(const float4*)(sSb + cc*S_CH_STRIDE + 8);
            f0.v = *(const float4*)(sFb + cc*F_CH_STRIDE);   // broadcast across dy lanes
            // P[i] = (sv[i], sv[i+1]), i = 0..10
            unsigned long long P[11];
            P[0]  = s0.u[0];  P[2]  = s0.u[1];
            P[4]  = s1.u[0];  P[6]  = s1.u[1];
            P[8]  = s2.u[0];  P[10] = s2.u[1];
            P[1]  = pack2(s0.f[1], s0.f[2]);
            P[3]  = pack2(s0.f[3], s1.f[0]);
            P[5]  = pack2(s1.f[1], s1.f[2]);
            P[7]  = pack2(s1.f[3], s2.f[0]);
            P[9]  = pack2(s2.f[1], s2.f[2]);
            #pragma unroll
            for (int dx = 0; dx < ND; dx++) {
                acc2[dx][0] = ffma2(f0.u[0], P[dx],     acc2[dx][0]);
                acc2[dx][1] = ffma2(f0.u[1], P[dx + 2], acc2[dx][1]);
            }
        }

        // this warp is done reading stage cons_s
        __syncwarp();
        if (lane == 0) mbar_arrive(mbar_base + 8*(NSTAGE + cons_s));
        if (++cons_s == NSTAGE) { cons_s = 0; cons_ph ^= 1; }
    }

    // ---- epilogue: scale by 1/C and store ----
    const float scale = 1.0f / (float)NC;
    float* obase = out + (((size_t)b * (ND*ND) + (size_t)dy * ND) * NH + (h0 + row)) * NW
                       + (w0 + x0);
    #pragma unroll
    for (int dx = 0; dx < ND; dx++) {
        float l0, h1, l2, h3;
        unpack2(acc2[dx][0], l0, h1);
        unpack2(acc2[dx][1], l2, h3);
        float4 v = make_float4(l0*scale, h1*scale, l2*scale, h3*scale);
        *(float4*)(obase + (size_t)dx * HW) = v;
    }
}

extern "C" void kernel_launch(void* const* d_in, const int* in_sizes, int n_in,
                              void* d_out, int out_size)
{
    const float* tenFirst  = (const float*)d_in[0];
    const float* tenSecond = (const float*)d_in[1];
    float* out = (float*)d_out;

    cudaFuncSetAttribute(corr_kernel,
                         cudaFuncAttributeMaxDynamicSharedMemorySize, SMEM_BYTES);

    dim3 grid(NW / TW, NH / TH, NB);   // 20 x 24 x 4 = 1920 blocks
    dim3 block(NTHR);
    corr_kernel<<<grid, block, SMEM_BYTES>>>(tenFirst, tenSecond, out);
}